// round 1
// baseline (speedup 1.0000x reference)
#include <cuda_runtime.h>

#define NPTS 4096
#define TPB 256
#define ITILES (NPTS / TPB)      // 16 i-tiles
#define JCHUNKS 37               // 16*37 = 592 blocks = 4 per SM (148 SMs), perfect balance
#define CHUNK 111                // ceil(4096/37)

// Static scratch (no allocation allowed in kernel_launch)
__device__ float4 g_A[NPTS];               // scaled train projections a
__device__ float4 g_A2[NPTS];              // a^2
__device__ float4 g_TB[NPTS];              // 2*b (scaled query projections, doubled)
__device__ float4 g_Y4[NPTS];              // Y rows padded to float4
__device__ float4 g_pden[JCHUNKS * NPTS];  // partial denominators
__device__ float4 g_pnum[JCHUNKS * NPTS];  // partial numerators

__device__ __forceinline__ float ex2f(float x) {
    float y;
    asm("ex2.approx.ftz.f32 %0, %1;" : "=f"(y) : "f"(x));
    return y;
}

// Stage 0: project x and train_X through W, fold all scalar factors in.
// s = sqrt(0.5 * log2(e)) / h   so   2^{-(a-b)^2} == exp(-0.5*((Ft-Fx)/h)^2)
__global__ void prep_kernel(const float* __restrict__ x,
                            const float* __restrict__ tx,
                            const float* __restrict__ Y,
                            const float* __restrict__ W,
                            const float* __restrict__ h) {
    int j = blockIdx.x * blockDim.x + threadIdx.x;
    if (j >= NPTS) return;
    float s = sqrtf(0.5f * 1.44269504088896340736f) / h[0];
    float4 xt = reinterpret_cast<const float4*>(tx)[j];  // train row, D_IN=4
    float4 xq = reinterpret_cast<const float4*>(x)[j];   // query row
    float a[3], b[3];
#pragma unroll
    for (int c = 0; c < 3; ++c) {
        float w0 = W[c*4+0], w1 = W[c*4+1], w2 = W[c*4+2], w3 = W[c*4+3];
        a[c] = (xt.x*w0 + xt.y*w1 + xt.z*w2 + xt.w*w3) * s;
        b[c] = (xq.x*w0 + xq.y*w1 + xq.z*w2 + xq.w*w3) * s;
    }
    g_A[j]  = make_float4(a[0], a[1], a[2], 0.f);
    g_A2[j] = make_float4(a[0]*a[0], a[1]*a[1], a[2]*a[2], 0.f);
    g_TB[j] = make_float4(b[0]+b[0], b[1]+b[1], b[2]+b[2], 0.f);
    g_Y4[j] = make_float4(Y[3*j+0], Y[3*j+1], Y[3*j+2], 0.f);
}

// Stage 1: the O(N^2*3) hot loop.
// k'_{j,i,c} = 2^{a_j*(2b_i) - a_j^2}   (the 2^{-b^2} factor cancels in the final ratio)
// Per pair-channel: 1 FFMA + 1 MUFU.EX2 + 1 FADD + 1 FFMA  -> MUFU-bound.
__global__ void __launch_bounds__(TPB, 4) pair_kernel() {
    __shared__ float4 sA[CHUNK], sA2[CHUNK], sY[CHUNK];
    int i  = blockIdx.x * TPB + threadIdx.x;   // query index (one per thread)
    int j0 = blockIdx.y * CHUNK;               // this block's j-chunk
    int jn = min(CHUNK, NPTS - j0);
    for (int t = threadIdx.x; t < jn; t += TPB) {
        sA[t]  = g_A[j0 + t];
        sA2[t] = g_A2[j0 + t];
        sY[t]  = g_Y4[j0 + t];
    }
    __syncthreads();
    float4 tb = g_TB[i];
    float d0 = 0.f, d1 = 0.f, d2 = 0.f;
    float n0 = 0.f, n1 = 0.f, n2 = 0.f;
#pragma unroll 3
    for (int t = 0; t < jn; ++t) {
        float4 a = sA[t];     // broadcast LDS.128 (all threads same j)
        float4 q = sA2[t];
        float4 y = sY[t];
        float k0 = ex2f(fmaf(a.x, tb.x, -q.x));
        float k1 = ex2f(fmaf(a.y, tb.y, -q.y));
        float k2 = ex2f(fmaf(a.z, tb.z, -q.z));
        d0 += k0; d1 += k1; d2 += k2;
        n0 = fmaf(k0, y.x, n0);
        n1 = fmaf(k1, y.y, n1);
        n2 = fmaf(k2, y.z, n2);
    }
    int idx = blockIdx.y * NPTS + i;
    g_pden[idx] = make_float4(d0, d1, d2, 0.f);
    g_pnum[idx] = make_float4(n0, n1, n2, 0.f);
}

// Stage 2: reduce partials over chunks, subtract the self-pair (leave-one-out),
// divide. Self term is computed with the bit-identical expression as the loop.
__global__ void fin_kernel(float* __restrict__ out) {
    int i = blockIdx.x * blockDim.x + threadIdx.x;
    if (i >= NPTS) return;
    float d0 = 0.f, d1 = 0.f, d2 = 0.f;
    float n0 = 0.f, n1 = 0.f, n2 = 0.f;
    for (int z = 0; z < JCHUNKS; ++z) {
        float4 pd = g_pden[z * NPTS + i];
        float4 pn = g_pnum[z * NPTS + i];
        d0 += pd.x; d1 += pd.y; d2 += pd.z;
        n0 += pn.x; n1 += pn.y; n2 += pn.z;
    }
    float4 a  = g_A[i];
    float4 q  = g_A2[i];
    float4 tb = g_TB[i];
    float4 y  = g_Y4[i];
    float k0 = ex2f(fmaf(a.x, tb.x, -q.x));
    float k1 = ex2f(fmaf(a.y, tb.y, -q.y));
    float k2 = ex2f(fmaf(a.z, tb.z, -q.z));
    out[3*i+0] = (n0 - k0 * y.x) / (d0 - k0);
    out[3*i+1] = (n1 - k1 * y.y) / (d1 - k1);
    out[3*i+2] = (n2 - k2 * y.z) / (d2 - k2);
}

extern "C" void kernel_launch(void* const* d_in, const int* in_sizes, int n_in,
                              void* d_out, int out_size) {
    const float* x  = (const float*)d_in[0];  // [4096,4]
    const float* tx = (const float*)d_in[1];  // [4096,4] train_X
    const float* Y  = (const float*)d_in[2];  // [4096,3]
    const float* W  = (const float*)d_in[3];  // [3,4]
    const float* h  = (const float*)d_in[4];  // [1]
    float* out = (float*)d_out;               // [4096,3]

    prep_kernel<<<ITILES, TPB>>>(x, tx, Y, W, h);
    pair_kernel<<<dim3(ITILES, JCHUNKS), TPB>>>();
    fin_kernel<<<ITILES, TPB>>>(out);
}

// round 2
// speedup vs baseline: 1.1020x; 1.1020x over previous
#include <cuda_runtime.h>

#define NPTS 4096
#define TPB 256
#define ITILES 16            // NPTS / TPB
#define JCHUNKS 37           // 16*37 = 592 blocks = exactly 4/SM on 148 SMs (one wave)
#define CHUNK 111            // ceil(4096/37); padded, branch-free
#define NBLOCKS (ITILES * JCHUNKS)

// Static scratch (no allocation allowed anywhere)
__device__ float4 g_pden[JCHUNKS * NPTS];
__device__ float4 g_pnum[JCHUNKS * NPTS];
__device__ unsigned g_ctr  = 0;   // reset to 0 by last fin block each call -> stateless
__device__ unsigned g_done = 0;

__device__ __forceinline__ float ex2f(float x) {
    float y;
    asm("ex2.approx.ftz.f32 %0, %1;" : "=f"(y) : "f"(x));
    return y;
}

// One kernel does everything.
//  k'_{j,i,c} = 2^{a_j*(2 b_i) - a_j^2}; the 2^{-b^2} factor cancels in the ratio.
//  s = sqrt(0.5*log2 e)/h folds h and exp->exp2 into the projections.
//  Per pair-channel hot cost: 1 FFMA + 1 MUFU.EX2 + 1 FADD + 1 FFMA  (MUFU-bound).
__global__ void __launch_bounds__(TPB, 4) fused_kernel(
    const float* __restrict__ x,   // [4096,4]
    const float* __restrict__ tx,  // [4096,4]
    const float* __restrict__ Y,   // [4096,3]
    const float* __restrict__ W,   // [3,4]
    const float* __restrict__ h,   // [1]
    float* __restrict__ out)       // [4096,3]
{
    __shared__ float4 sA[CHUNK], sQ[CHUNK], sY[CHUNK];

    const float s = sqrtf(0.5f * 1.44269504088896340736f) / h[0];
    const float w0 = W[0], w1 = W[1], w2  = W[2],  w3  = W[3];
    const float w4 = W[4], w5 = W[5], w6  = W[6],  w7  = W[7];
    const float w8 = W[8], w9 = W[9], w10 = W[10], w11 = W[11];

    // ---- in-block prep of this chunk's j data (replaces prep_kernel) ----
    const int j0 = blockIdx.y * CHUNK;
    for (int t = threadIdx.x; t < CHUNK; t += TPB) {
        int j = j0 + t;
        if (j < NPTS) {
            float4 xt = __ldg(reinterpret_cast<const float4*>(tx) + j);
            float a0 = (xt.x*w0 + xt.y*w1 + xt.z*w2  + xt.w*w3 ) * s;
            float a1 = (xt.x*w4 + xt.y*w5 + xt.z*w6  + xt.w*w7 ) * s;
            float a2 = (xt.x*w8 + xt.y*w9 + xt.z*w10 + xt.w*w11) * s;
            sA[t] = make_float4(a0, a1, a2, 0.f);
            sQ[t] = make_float4(a0*a0, a1*a1, a2*a2, 0.f);
            sY[t] = make_float4(Y[3*j+0], Y[3*j+1], Y[3*j+2], 0.f);
        } else {
            // padding: arg = 0*tb - 3e38 -> ex2 flushes to 0, contributes nothing
            sA[t] = make_float4(0.f, 0.f, 0.f, 0.f);
            sQ[t] = make_float4(3e38f, 3e38f, 3e38f, 0.f);
            sY[t] = make_float4(0.f, 0.f, 0.f, 0.f);
        }
    }

    // ---- per-thread query projection ----
    const int i = blockIdx.x * TPB + threadIdx.x;
    float4 xq = __ldg(reinterpret_cast<const float4*>(x) + i);
    const float tb0 = 2.f * ((xq.x*w0 + xq.y*w1 + xq.z*w2  + xq.w*w3 ) * s);
    const float tb1 = 2.f * ((xq.x*w4 + xq.y*w5 + xq.z*w6  + xq.w*w7 ) * s);
    const float tb2 = 2.f * ((xq.x*w8 + xq.y*w9 + xq.z*w10 + xq.w*w11) * s);
    __syncthreads();

    // ---- O(N^2*3) hot loop, fixed trip count, branch-free ----
    float d0 = 0.f, d1 = 0.f, d2 = 0.f;
    float n0 = 0.f, n1 = 0.f, n2 = 0.f;
#pragma unroll 3
    for (int t = 0; t < CHUNK; ++t) {
        float4 a = sA[t];   // broadcast LDS.128
        float4 q = sQ[t];
        float4 y = sY[t];
        float k0 = ex2f(fmaf(a.x, tb0, -q.x));
        float k1 = ex2f(fmaf(a.y, tb1, -q.y));
        float k2 = ex2f(fmaf(a.z, tb2, -q.z));
        d0 += k0; d1 += k1; d2 += k2;
        n0 = fmaf(k0, y.x, n0);
        n1 = fmaf(k1, y.y, n1);
        n2 = fmaf(k2, y.z, n2);
    }
    const int pidx = blockIdx.y * NPTS + i;
    g_pden[pidx] = make_float4(d0, d1, d2, 0.f);
    g_pnum[pidx] = make_float4(n0, n1, n2, 0.f);

    // ---- publish partial: fence + ticket ----
    __threadfence();
    __syncthreads();
    if (threadIdx.x == 0) atomicAdd(&g_ctr, 1u);

    // ---- blocks with blockIdx.y==0 (16 blocks = 4096 threads) do the finalize ----
    if (blockIdx.y != 0) return;

    if (threadIdx.x == 0) {
        while (*((volatile unsigned*)&g_ctr) < NBLOCKS) __nanosleep(40);
    }
    __syncthreads();
    __threadfence();  // acquire: partials now visible

    float D0 = 0.f, D1 = 0.f, D2 = 0.f;
    float N0 = 0.f, N1 = 0.f, N2 = 0.f;
#pragma unroll
    for (int z = 0; z < JCHUNKS; ++z) {
        float4 pd = g_pden[z * NPTS + i];
        float4 pn = g_pnum[z * NPTS + i];
        D0 += pd.x; D1 += pd.y; D2 += pd.z;
        N0 += pn.x; N1 += pn.y; N2 += pn.z;
    }

    // self-pair (leave-one-out), same formulas as the chunk prep above
    float4 xt = __ldg(reinterpret_cast<const float4*>(tx) + i);
    float a0 = (xt.x*w0 + xt.y*w1 + xt.z*w2  + xt.w*w3 ) * s;
    float a1 = (xt.x*w4 + xt.y*w5 + xt.z*w6  + xt.w*w7 ) * s;
    float a2 = (xt.x*w8 + xt.y*w9 + xt.z*w10 + xt.w*w11) * s;
    float k0 = ex2f(fmaf(a0, tb0, -(a0*a0)));
    float k1 = ex2f(fmaf(a1, tb1, -(a1*a1)));
    float k2 = ex2f(fmaf(a2, tb2, -(a2*a2)));
    float y0 = Y[3*i+0], y1 = Y[3*i+1], y2 = Y[3*i+2];

    out[3*i+0] = (N0 - k0*y0) / (D0 - k0);
    out[3*i+1] = (N1 - k1*y1) / (D1 - k1);
    out[3*i+2] = (N2 - k2*y2) / (D2 - k2);

    // ---- reset counters so every call starts from a clean state ----
    __syncthreads();
    if (threadIdx.x == 0) {
        unsigned v = atomicAdd(&g_done, 1u);
        if (v == ITILES - 1) { g_ctr = 0; g_done = 0; __threadfence(); }
    }
}

extern "C" void kernel_launch(void* const* d_in, const int* in_sizes, int n_in,
                              void* d_out, int out_size) {
    const float* x  = (const float*)d_in[0];
    const float* tx = (const float*)d_in[1];
    const float* Y  = (const float*)d_in[2];
    const float* W  = (const float*)d_in[3];
    const float* h  = (const float*)d_in[4];
    float* out = (float*)d_out;

    fused_kernel<<<dim3(ITILES, JCHUNKS), TPB>>>(x, tx, Y, W, h, out);
}

// round 5
// speedup vs baseline: 1.4400x; 1.3067x over previous
#include <cuda_runtime.h>

#define NPTS 4096
#define TPB 256
#define ITILES 8             // i-tiles of 512 (2 i's per thread)
#define JCHUNKS 74           // 8*74 = 592 blocks = one wave @ 4 CTAs/SM on 148 SMs
#define CHUNK 56             // 74*56 = 4144 >= 4096, padded, branch-free
#define NBLOCKS (ITILES * JCHUNKS)
#define FINB 64              // fin blocks: 64 blocks x 64 i's x 4-way z-split

__device__ float4 g_pden[JCHUNKS * NPTS];
__device__ float4 g_pnum[JCHUNKS * NPTS];
__device__ unsigned g_ctr  = 0;
__device__ unsigned g_done = 0;

__device__ __forceinline__ float ex2f(float x) {
    float y;
    asm("ex2.approx.ftz.f32 %0, %1;" : "=f"(y) : "f"(x));
    return y;
}

// dot(row4, W[c*4..]) with a FIXED fma order so prep and fin produce identical bits
__device__ __forceinline__ float dotw(float4 r, const float* __restrict__ W, int c) {
    float d = r.x * __ldg(W + c*4 + 0);
    d = fmaf(r.y, __ldg(W + c*4 + 1), d);
    d = fmaf(r.z, __ldg(W + c*4 + 2), d);
    d = fmaf(r.w, __ldg(W + c*4 + 3), d);
    return d;
}

// k'_{j,i,c} = 2^{a_j*(2 b_i) - a_j^2}; the per-i factor 2^{-b^2} cancels in the ratio.
// s = sqrt(0.5*log2 e)/h. Hot cost per pair-channel: 1 FFMA + 1 EX2 + 1 FADD + 1 FFMA.
__global__ void __launch_bounds__(TPB, 4) fused_kernel(
    const float* __restrict__ x,   // [4096,4]
    const float* __restrict__ tx,  // [4096,4]
    const float* __restrict__ Y,   // [4096,3]
    const float* __restrict__ W,   // [3,4]
    const float* __restrict__ h,   // [1]
    float* __restrict__ out)       // [4096,3]
{
    __shared__ float4 sA[CHUNK], sQ[CHUNK], sY[CHUNK];
    __shared__ float sRed[3][FINB][8];   // fin z-split combine buffer

    const int tid = threadIdx.x;
    const float s  = sqrtf(0.5f * 1.44269504088896340736f) / __ldg(h);
    const float s2 = s + s;

    // ---- prep this block's j-chunk into smem (threads 0..CHUNK-1, one row each) ----
    const int j0 = blockIdx.y * CHUNK;
    if (tid < CHUNK) {
        int j = j0 + tid;
        if (j < NPTS) {
            float4 xt = __ldg(reinterpret_cast<const float4*>(tx) + j);
            float a0 = dotw(xt, W, 0) * s;
            float a1 = dotw(xt, W, 1) * s;
            float a2 = dotw(xt, W, 2) * s;
            sA[tid] = make_float4(a0, a1, a2, 0.f);
            sQ[tid] = make_float4(a0*a0, a1*a1, a2*a2, 0.f);
            sY[tid] = make_float4(__ldg(Y+3*j), __ldg(Y+3*j+1), __ldg(Y+3*j+2), 0.f);
        } else {
            sA[tid] = make_float4(0.f, 0.f, 0.f, 0.f);
            sQ[tid] = make_float4(3e38f, 3e38f, 3e38f, 0.f); // ex2(-3e38) -> 0
            sY[tid] = make_float4(0.f, 0.f, 0.f, 0.f);
        }
    }

    // ---- two query points per thread ----
    const int iA = blockIdx.x * (2*TPB) + tid;
    const int iB = iA + TPB;
    float4 xqA = __ldg(reinterpret_cast<const float4*>(x) + iA);
    float4 xqB = __ldg(reinterpret_cast<const float4*>(x) + iB);
    const float tA0 = dotw(xqA, W, 0) * s2, tA1 = dotw(xqA, W, 1) * s2, tA2 = dotw(xqA, W, 2) * s2;
    const float tB0 = dotw(xqB, W, 0) * s2, tB1 = dotw(xqB, W, 1) * s2, tB2 = dotw(xqB, W, 2) * s2;
    __syncthreads();

    // ---- hot loop: each j-row feeds 6 EX2 (3 channels x 2 queries) ----
    float dA0=0.f,dA1=0.f,dA2=0.f, nA0=0.f,nA1=0.f,nA2=0.f;
    float dB0=0.f,dB1=0.f,dB2=0.f, nB0=0.f,nB1=0.f,nB2=0.f;
#pragma unroll 4
    for (int t = 0; t < CHUNK; ++t) {
        float4 a = sA[t];   // broadcast LDS.128
        float4 q = sQ[t];
        float4 y = sY[t];
        float e;
        e = ex2f(fmaf(a.x, tA0, -q.x)); dA0 += e; nA0 = fmaf(e, y.x, nA0);
        e = ex2f(fmaf(a.y, tA1, -q.y)); dA1 += e; nA1 = fmaf(e, y.y, nA1);
        e = ex2f(fmaf(a.z, tA2, -q.z)); dA2 += e; nA2 = fmaf(e, y.z, nA2);
        e = ex2f(fmaf(a.x, tB0, -q.x)); dB0 += e; nB0 = fmaf(e, y.x, nB0);
        e = ex2f(fmaf(a.y, tB1, -q.y)); dB1 += e; nB1 = fmaf(e, y.y, nB1);
        e = ex2f(fmaf(a.z, tB2, -q.z)); dB2 += e; nB2 = fmaf(e, y.z, nB2);
    }
    g_pden[blockIdx.y * NPTS + iA] = make_float4(dA0, dA1, dA2, 0.f);
    g_pnum[blockIdx.y * NPTS + iA] = make_float4(nA0, nA1, nA2, 0.f);
    g_pden[blockIdx.y * NPTS + iB] = make_float4(dB0, dB1, dB2, 0.f);
    g_pnum[blockIdx.y * NPTS + iB] = make_float4(nB0, nB1, nB2, 0.f);

    // ---- publish ----
    __threadfence();
    __syncthreads();
    if (tid == 0) atomicAdd(&g_ctr, 1u);

    // ---- finalize: first FINB blocks (flat order), 4-way z-split per i ----
    const int flat = blockIdx.y * ITILES + blockIdx.x;
    if (flat >= FINB) return;

    if (tid == 0) {
        while (*((volatile unsigned*)&g_ctr) < NBLOCKS) __nanosleep(32);
    }
    __syncthreads();
    __threadfence();  // acquire

    const int ii = tid & (FINB - 1);       // 0..63
    const int zg = tid >> 6;               // 0..3
    const int i  = flat * FINB + ii;
    const int z0 = zg * 19;
    const int z1 = min(JCHUNKS, z0 + 19);

    float D0=0.f,D1=0.f,D2=0.f, N0=0.f,N1=0.f,N2=0.f;
    for (int z = z0; z < z1; ++z) {
        float4 pd = g_pden[z * NPTS + i];
        float4 pn = g_pnum[z * NPTS + i];
        D0 += pd.x; D1 += pd.y; D2 += pd.z;
        N0 += pn.x; N1 += pn.y; N2 += pn.z;
    }
    if (zg > 0) {
        sRed[zg-1][ii][0] = D0; sRed[zg-1][ii][1] = D1; sRed[zg-1][ii][2] = D2;
        sRed[zg-1][ii][3] = N0; sRed[zg-1][ii][4] = N1; sRed[zg-1][ii][5] = N2;
    }
    __syncthreads();
    if (zg == 0) {
#pragma unroll
        for (int g = 0; g < 3; ++g) {
            D0 += sRed[g][ii][0]; D1 += sRed[g][ii][1]; D2 += sRed[g][ii][2];
            N0 += sRed[g][ii][3]; N1 += sRed[g][ii][4]; N2 += sRed[g][ii][5];
        }
        // self-pair (leave-one-out): bit-identical recompute of the in-loop term
        float4 xt = __ldg(reinterpret_cast<const float4*>(tx) + i);
        float4 xq = __ldg(reinterpret_cast<const float4*>(x) + i);
        float a0 = dotw(xt, W, 0) * s, a1 = dotw(xt, W, 1) * s, a2 = dotw(xt, W, 2) * s;
        float t0 = dotw(xq, W, 0) * s2, t1 = dotw(xq, W, 1) * s2, t2 = dotw(xq, W, 2) * s2;
        float k0 = ex2f(fmaf(a0, t0, -(a0*a0)));
        float k1 = ex2f(fmaf(a1, t1, -(a1*a1)));
        float k2 = ex2f(fmaf(a2, t2, -(a2*a2)));
        float y0 = __ldg(Y+3*i), y1 = __ldg(Y+3*i+1), y2 = __ldg(Y+3*i+2);
        out[3*i+0] = (N0 - k0*y0) / (D0 - k0);
        out[3*i+1] = (N1 - k1*y1) / (D1 - k1);
        out[3*i+2] = (N2 - k2*y2) / (D2 - k2);
    }

    // ---- reset counters for the next graph replay ----
    __syncthreads();
    if (tid == 0) {
        unsigned v = atomicAdd(&g_done, 1u);
        if (v == FINB - 1) { g_ctr = 0; g_done = 0; __threadfence(); }
    }
}

extern "C" void kernel_launch(void* const* d_in, const int* in_sizes, int n_in,
                              void* d_out, int out_size) {
    const float* x  = (const float*)d_in[0];
    const float* tx = (const float*)d_in[1];
    const float* Y  = (const float*)d_in[2];
    const float* W  = (const float*)d_in[3];
    const float* h  = (const float*)d_in[4];
    float* out = (float*)d_out;

    fused_kernel<<<dim3(ITILES, JCHUNKS), TPB>>>(x, tx, Y, W, h, out);
}